// round 9
// baseline (speedup 1.0000x reference)
#include <cuda_runtime.h>
typedef unsigned int u32; typedef unsigned long long u64; typedef unsigned short u16;
#define NB 64
#define NN 512
#define NF 64

__device__ __align__(16) float g_Yrow[NB*NN*NF];     // Y=XW*cs row-major (diag adds)
__device__ __align__(16) uint4 g_Yfr [NB*64*8*32];   // [b][qj][n][lane] tf32 hi/lo frags of Y (P-gemm B)
__device__ __align__(16) uint4 g_XWfr[NB*8*8*8*32];  // [b][kt][qf][n][lane] tf32 frags of XW (S-gemm B)
__device__ __align__(16) uint4 g_XTfr[NB*8*4*8*32];  // [b][kt][qk][n][lane] bf16 frags of XW^T (H-gemm B)

__device__ __forceinline__ u32 smaddr(const void* p){
    u32 a; asm("{.reg .u64 t; cvta.to.shared.u64 t,%1; cvt.u32.u64 %0,t;}":"=r"(a):"l"(p)); return a;
}
__device__ __forceinline__ u32 t32(float x){ u32 r; asm("cvt.rna.tf32.f32 %0,%1;":"=r"(r):"f"(x)); return r; }
__device__ __forceinline__ void tsplit(float x, u32& h, u32& l){ h=t32(x); l=t32(x-__uint_as_float(h)); }
__device__ __forceinline__ u32 cvt2(float hi,float lo){ u32 r; asm("cvt.rn.bf16x2.f32 %0,%1,%2;":"=r"(r):"f"(hi),"f"(lo)); return r; }
__device__ __forceinline__ float bflo(u32 p){ return __uint_as_float(p<<16); }
__device__ __forceinline__ float bfhi(u32 p){ return __uint_as_float(p&0xFFFF0000u); }
__device__ __forceinline__ float tanhf_(float x){ float y; asm("tanh.approx.f32 %0,%1;":"=f"(y):"f"(x)); return y; }

#define MMAT(d,a,b0,b1) asm volatile( \
 "mma.sync.aligned.m16n8k8.row.col.f32.tf32.tf32.f32 {%0,%1,%2,%3},{%4,%5,%6,%7},{%8,%9},{%0,%1,%2,%3};" \
 : "+f"((d)[0]),"+f"((d)[1]),"+f"((d)[2]),"+f"((d)[3]) \
 : "r"((a)[0]),"r"((a)[1]),"r"((a)[2]),"r"((a)[3]),"r"(b0),"r"(b1))
#define MMAB(d,a,b0,b1) asm volatile( \
 "mma.sync.aligned.m16n8k16.row.col.f32.bf16.bf16.f32 {%0,%1,%2,%3},{%4,%5,%6,%7},{%8,%9},{%0,%1,%2,%3};" \
 : "+f"((d)[0]),"+f"((d)[1]),"+f"((d)[2]),"+f"((d)[3]) \
 : "r"((a)[0]),"r"((a)[1]),"r"((a)[2]),"r"((a)[3]),"r"(b0),"r"(b1))
#define CPA(dst,src) asm volatile("cp.async.cg.shared.global [%0],[%1],16;"::"r"(dst),"l"(src):"memory")
#define CPC() asm volatile("cp.async.commit_group;":::"memory")
#define CPW(n) asm volatile("cp.async.wait_group %0;"::"n"(n):"memory")

// ---------------------------------------------------------------------------
// XW = X@W per 64-row tile; col_sum(a) computed locally; emit Yrow fp32 +
// fragment-packed B operands for all three gemms.
__global__ __launch_bounds__(256) void k_prep(const float* __restrict__ X, const float* __restrict__ W,
                                              const float* __restrict__ am){
    __shared__ __align__(16) float Ws[64][64];
    __shared__ __align__(16) float Xs[64][68];
    __shared__ float csp[4][64];
    __shared__ float csm[64];
    const int t=threadIdx.x, b=blockIdx.x>>3, kt=blockIdx.x&7, R0=blockIdx.x*64;
    {   // col_sum of a: 4 partial rows-of-16 per column
        int f=t&63, seg=t>>6;
        float s=0.f;
        for(int i=seg;i<64;i+=4) s+=am[i*64+f];
        csp[seg][f]=s;
    }
    for(int i=t;i<64*64;i+=256) Ws[i>>6][i&63]=W[i];
    for(int i=t;i<64*64;i+=256) Xs[i>>6][i&63]=X[(size_t)(R0+(i>>6))*NF+(i&63)];
    __syncthreads();
    if(t<64) csm[t]=csp[0][t]+csp[1][t]+csp[2][t]+csp[3][t];
    {
        const int tx=t&15, ty=t>>4;
        float acc[4][4]={};
        for(int c=0;c<64;c++){
            float xv[4],wv[4];
#pragma unroll
            for(int ii=0;ii<4;ii++) xv[ii]=Xs[ty*4+ii][c];
#pragma unroll
            for(int jj=0;jj<4;jj++) wv[jj]=Ws[c][tx*4+jj];
#pragma unroll
            for(int ii=0;ii<4;ii++)
#pragma unroll
                for(int jj=0;jj<4;jj++) acc[ii][jj]+=xv[ii]*wv[jj];
        }
        __syncthreads();
#pragma unroll
        for(int ii=0;ii<4;ii++)
#pragma unroll
            for(int jj=0;jj<4;jj++) Xs[ty*4+ii][tx*4+jj]=acc[ii][jj];
    }
    __syncthreads();
    const int lane=t&31, g=lane>>2, tc=lane&3;
    // Yrow fp32
#pragma unroll
    for(int u=0;u<4;u++){
        int idx=t+256*u; int r=idx>>4, f4=idx&15;
        float4 v=*(float4*)&Xs[r][f4*4];
        v.x*=csm[f4*4]; v.y*=csm[f4*4+1]; v.z*=csm[f4*4+2]; v.w*=csm[f4*4+3];
        *(float4*)&g_Yrow[(size_t)(R0+r)*NF+f4*4]=v;
    }
    // Y frags (tf32): element (j=q*8+tc(+4), f=n*8+g)
#pragma unroll
    for(int u=0;u<8;u++){
        int idx=t+256*u; int n=(idx>>5)&7, q=idx>>8;
        int f=n*8+g; float cf=csm[f];
        uint4 v;
        tsplit(Xs[q*8+tc][f]*cf,   v.x, v.y);
        tsplit(Xs[q*8+tc+4][f]*cf, v.z, v.w);
        g_Yfr[((size_t)(b*64+kt*8+q)*8+n)*32+lane]=v;
    }
    // XW frags (tf32): element (k=n*8+g, f=qf*8+tc(+4))
#pragma unroll
    for(int u=0;u<8;u++){
        int idx=t+256*u; int n=(idx>>5)&7, qf=idx>>8;
        int kr=n*8+g;
        uint4 v;
        tsplit(Xs[kr][qf*8+tc],   v.x, v.y);
        tsplit(Xs[kr][qf*8+tc+4], v.z, v.w);
        g_XWfr[(((size_t)(b*8+kt)*8+qf)*8+n)*32+lane]=v;
    }
    // XT frags (bf16 pairs): element (k=qk*16+2tc(+1,+8,+9), d=n*8+g)
#pragma unroll
    for(int u=0;u<4;u++){
        int idx=t+256*u; int n=(idx>>5)&7, qk=idx>>8;
        int d=n*8+g, k0=qk*16+2*tc;
        float x0=Xs[k0][d], x1=Xs[k0+1][d], x2=Xs[k0+8][d], x3=Xs[k0+9][d];
        uint4 v;
        v.x=cvt2(x1,x0); v.z=cvt2(x1-bfhi(v.x), x0-bflo(v.x));
        v.y=cvt2(x3,x2); v.w=cvt2(x3-bfhi(v.y), x2-bflo(v.y));
        g_XTfr[(((size_t)(b*8+kt)*4+qk)*8+n)*32+lane]=v;
    }
}

// ---------------------------------------------------------------------------
// smem map (bytes): P[0,34816) | XWf[34816,67584) | XTf[67584,83968) | rs@83968 | bas@84480
// phase-A aliases: A0[0,18432) A1[18432,36864) Yf0[36864,53248) Yf1[53248,69632)
#define SMEMB 86528
__global__ __launch_bounds__(256,2) void k_main(const float* __restrict__ A, const float* __restrict__ ba,
                                                const float* __restrict__ bW, float* __restrict__ H,
                                                const int* __restrict__ N32){
    extern __shared__ __align__(16) char sm[];
    float* Ps =(float*)sm;
    char*  XWf= sm+34816;
    char*  XTf= sm+67584;
    float* rs =(float*)(sm+83968);
    float* bas=(float*)(sm+84480);
    const int t=threadIdx.x, w=t>>5, lane=t&31, g=lane>>2, tc=lane&3;
    const int b=blockIdx.y, i0=blockIdx.x*128;
    const u32 sbase=smaddr(sm);
    bas[t]=ba[t]; bas[256+t]=ba[256+t];
    // N decode: int32 storage => odd word N32[1]>=1; int64 (LE) => hi word == 0
    const int nb = (__ldg(&N32[1])!=0) ? __ldg(&N32[b]) : __ldg(&N32[2*b]);
    const float* Ab = A + ((size_t)b*NN+i0)*NN;

    auto issueA=[&](int p,int it){
        const int j0=it*32;
#pragma unroll
        for(int u=0;u<4;u++){
            int idx=t+256*u; int r=idx>>3, c=idx&7;
            CPA(sbase + p*18432 + (u32)(r*36+c*4)*4, Ab + (size_t)r*NN + j0 + c*4);
        }
        const uint4* src=g_Yfr + (size_t)(b*64+it*4)*256;
#pragma unroll
        for(int u=0;u<4;u++){
            int idx=t+256*u;
            CPA(sbase + 36864 + p*16384 + (u32)idx*16, src+idx);
        }
        CPC();
    };

    // ---- phase A: pacc = A @ Y over K=512 (16 iters of 32) ----
    float pacc[8][4]={}; float rloc=0.f;
    issueA(0,0);
    for(int it=0; it<16; it++){
        const int p=it&1;
        if(it<15){ issueA(p^1,it+1); CPW(1); } else CPW(0);
        __syncthreads();
        const float* As=(const float*)(sm + p*18432);
        if(t<128){
            float s=0.f;
#pragma unroll
            for(int c=0;c<8;c++){ float4 v=*(const float4*)&As[t*36+c*4]; s+=v.x+v.y+v.z+v.w; }
            rloc+=s;
        }
        const char* Yb = sm + 36864 + p*16384;
#pragma unroll
        for(int q=0;q<4;q++){
            u32 ah[4],al[4];
            tsplit(As[(w*16+g  )*36+q*8+tc  ], ah[0],al[0]);
            tsplit(As[(w*16+g+8)*36+q*8+tc  ], ah[1],al[1]);
            tsplit(As[(w*16+g  )*36+q*8+tc+4], ah[2],al[2]);
            tsplit(As[(w*16+g+8)*36+q*8+tc+4], ah[3],al[3]);
            const uint4* yb=(const uint4*)(Yb + q*4096) + lane;
#pragma unroll
            for(int n=0;n<8;n++){
                uint4 v=yb[n*32];
                MMAT(pacc[n],ah,v.x,v.z);
                MMAT(pacc[n],ah,v.y,v.w);
                MMAT(pacc[n],al,v.x,v.z);
            }
        }
        __syncthreads();
    }
    if(t<128) rs[t]=rloc + ((i0+t)<nb ? 1.f : 0.f);

    // ---- prefetch XWf(kt=0) (overlaps P epilogue; phase-A buffers drained) ----
    {
        const uint4* sw=g_XWfr + (size_t)(b*8)*2048;
#pragma unroll
        for(int u=0;u<8;u++){ int idx=t+256*u; CPA(sbase+34816+(u32)idx*16, sw+idx); }
        CPC();
    }

    // ---- diag add + store P to smem fp32 ----
    {
        const int il=i0+w*16+g, ih=il+8;
        const float* Yr=g_Yrow + (size_t)b*NN*NF;
#pragma unroll
        for(int n=0;n<8;n++){
            const int f=n*8+2*tc;
            if(il<nb){ pacc[n][0]+=Yr[(size_t)il*NF+f]; pacc[n][1]+=Yr[(size_t)il*NF+f+1]; }
            if(ih<nb){ pacc[n][2]+=Yr[(size_t)ih*NF+f]; pacc[n][3]+=Yr[(size_t)ih*NF+f+1]; }
            Ps[(w*16+g  )*68+f]  =pacc[n][0];
            Ps[(w*16+g  )*68+f+1]=pacc[n][1];
            Ps[(w*16+g+8)*68+f]  =pacc[n][2];
            Ps[(w*16+g+8)*68+f+1]=pacc[n][3];
        }
    }
    __syncthreads();

    // ---- phase B: S = tanh(P@XW^T + r*ba) [3xTF32]; H += S@XW [bf16 3-term] ----
    // Pipelined: XTf(kt) issued at top (hidden under S-gemm); XWf(kt+1) issued
    // after S-gemm (hidden under H-gemm). Single buffers, 2 commit groups in flight.
    float hacc[8][4]={};
    const float rv0=rs[w*16+g], rv1=rs[w*16+g+8];
    for(int kt=0;kt<8;kt++){
        __syncthreads();  // all warps past H-gemm(kt-1): XTf buffer free
        {
            const uint4* st=g_XTfr + (size_t)(b*8+kt)*1024;
#pragma unroll
            for(int u=0;u<4;u++){ int idx=t+256*u; CPA(sbase+67584+(u32)idx*16, st+idx); }
            CPC();
        }
        CPW(1);           // XWf(kt) (older group) done; XTf(kt) may still fly
        __syncthreads();
        float sacc[8][4]={};
#pragma unroll
        for(int qf=0;qf<8;qf++){
            u32 ph[4],pl[4];
            tsplit(Ps[(w*16+g  )*68+qf*8+tc  ], ph[0],pl[0]);
            tsplit(Ps[(w*16+g+8)*68+qf*8+tc  ], ph[1],pl[1]);
            tsplit(Ps[(w*16+g  )*68+qf*8+tc+4], ph[2],pl[2]);
            tsplit(Ps[(w*16+g+8)*68+qf*8+tc+4], ph[3],pl[3]);
            const uint4* wb=(const uint4*)XWf + qf*256 + lane;
#pragma unroll
            for(int n=0;n<8;n++){
                uint4 v=wb[n*32];
                MMAT(sacc[n],ph,v.x,v.z);
                MMAT(sacc[n],ph,v.y,v.w);
                MMAT(sacc[n],pl,v.x,v.z);
            }
        }
        __syncthreads();  // all warps done reading XWf(kt)
        if(kt<7){
            const uint4* sw=g_XWfr + (size_t)(b*8+kt+1)*2048;
#pragma unroll
            for(int u=0;u<8;u++){ int idx=t+256*u; CPA(sbase+34816+(u32)idx*16, sw+idx); }
            CPC();
            CPW(1);       // XTf(kt) done; XWf(kt+1) may fly
        } else {
            CPW(0);
        }
        __syncthreads();
#pragma unroll
        for(int qk=0;qk<4;qk++){
            u32 Sh[4],Sl[4];
#pragma unroll
            for(int qq=0;qq<2;qq++){
                const int n=2*qk+qq;
                const int kc=kt*64+n*8+2*tc;
                const float b0v=bas[kc], b1v=bas[kc+1];
                float s0=tanhf_(sacc[n][0]+rv0*b0v);
                float s1=tanhf_(sacc[n][1]+rv0*b1v);
                float s2=tanhf_(sacc[n][2]+rv1*b0v);
                float s3=tanhf_(sacc[n][3]+rv1*b1v);
                Sh[2*qq]  =cvt2(s1,s0); Sl[2*qq]  =cvt2(s1-bfhi(Sh[2*qq]),  s0-bflo(Sh[2*qq]));
                Sh[2*qq+1]=cvt2(s3,s2); Sl[2*qq+1]=cvt2(s3-bfhi(Sh[2*qq+1]),s2-bflo(Sh[2*qq+1]));
            }
            const uint4* tb=(const uint4*)XTf + qk*256 + lane;
#pragma unroll
            for(int n=0;n<8;n++){
                uint4 v=tb[n*32];
                MMAB(hacc[n],Sh,v.x,v.y);
                MMAB(hacc[n],Sh,v.z,v.w);
                MMAB(hacc[n],Sl,v.x,v.y);
            }
        }
    }

    // ---- epilogue ----
    {
        const int il=i0+w*16+g, ih=il+8;
#pragma unroll
        for(int n=0;n<8;n++){
            const int d=n*8+2*tc;
            float2 v0, v1;
            v0.x=hacc[n][0]+bW[d]; v0.y=hacc[n][1]+bW[d+1];
            v1.x=hacc[n][2]+bW[d]; v1.y=hacc[n][3]+bW[d+1];
            *(float2*)&H[((size_t)b*NN+il)*NF+d]=v0;
            *(float2*)&H[((size_t)b*NN+ih)*NF+d]=v1;
        }
    }
}

// ---------------------------------------------------------------------------
extern "C" void kernel_launch(void* const* d_in, const int* in_sizes, int n_in,
                              void* d_out, int out_size){
    const float* X =(const float*)d_in[0];
    const float* A =(const float*)d_in[1];
    const int*   N =(const int*)d_in[2];
    const float* W =(const float*)d_in[3];
    const float* a =(const float*)d_in[4];
    const float* bW=(const float*)d_in[5];
    const float* ba=(const float*)d_in[6];
    float* H=(float*)d_out;
    cudaFuncSetAttribute(k_main, cudaFuncAttributeMaxDynamicSharedMemorySize, SMEMB);
    k_prep<<<NB*8,256>>>(X,W,a);
    k_main<<<dim3(4,NB),256,SMEMB>>>(A,ba,bW,H,N);
}